// round 17
// baseline (speedup 1.0000x reference)
#include <cuda_runtime.h>

// SmoothAPLoss via dual histogram (NB=1024), minimal-depth pipeline.
//   total = sum_b [ pcnt[b]*ssum[b] - scnt[b]*psum[b] ],  ssum/scnt = inclusive
//   suffix sums of the negative histogram; npos = sum_b pcnt[b].
// 8 blocks x 1024 threads, 2 contiguous items/thread (one LDG.128 + LDG.64).
// Phase 1 into block-local SMEM (ATOMS, ~zero contention); merge = 1 bin/thread,
// <=4 adjacent predicated REDGs into interleaved float4 g_hist (<=16 writers/cell).
// Last block: 1 bin/thread tail (one LDG.128, 2-barrier scan, 1 dot term).
// All state self-cleans for graph replay.

#define DELTA 0.01f
#define NB    1024
#define TPB   1024

__device__ __align__(16) float4 g_hist[NB];   // {ncnt, nsum, pcnt, psum}
__device__ int g_done;

__device__ __forceinline__ float warp_suffix_incl(float v, int lane) {
#pragma unroll
    for (int off = 1; off < 32; off <<= 1) {
        float o = __shfl_down_sync(0xFFFFFFFFu, v, off);
        if (lane + off < 32) v += o;
    }
    return v;
}

__device__ __forceinline__ void hist_item(float4* sh, float x0, float x1, int l) {
    float p = __fdividef(1.0f, 1.0f + __expf(x0 - x1));
    bool is_pos = (l == 1);
    float val = is_pos ? (p - DELTA) : p;
    int b = max(0, min((int)(val * (float)NB), NB - 1));
    float* cell = (float*)&sh[b] + (is_pos ? 2 : 0);
    atomicAdd(cell, 1.0f);
    atomicAdd(cell + 1, val);
}

__global__ void __launch_bounds__(TPB)
fused_kernel(const float2* __restrict__ pred, const int* __restrict__ lab,
             int n, float* __restrict__ out) {
    __shared__ float4 sh[NB];        // block-local {ncnt, nsum, pcnt, psum}
    const int tid = threadIdx.x;
    const int lane = tid & 31;
    const int wid = tid >> 5;

    // zero block-local histogram (1 bin per thread)
    sh[tid] = make_float4(0.f, 0.f, 0.f, 0.f);
    __syncthreads();

    // ---- phase 1: 2 contiguous items per thread (LDG.128 + LDG.64) ----
    int i0 = blockIdx.x * (TPB * 2) + tid * 2;
    if (i0 + 1 < n) {
        float4 x = ((const float4*)pred)[i0 >> 1];
        int2 l = ((const int2*)lab)[i0 >> 1];
        hist_item(sh, x.x, x.y, l.x);
        hist_item(sh, x.z, x.w, l.y);
    } else if (i0 < n) {
        float2 x = pred[i0];
        hist_item(sh, x.x, x.y, lab[i0]);
    }
    __syncthreads();

    // ---- merge: 1 bin per thread, <=4 adjacent predicated REDGs ----
    {
        float4 h = sh[tid];
        float* g = (float*)&g_hist[tid];
        if (h.x != 0.0f) {
            atomicAdd(g + 0, h.x);
            atomicAdd(g + 1, h.y);
        }
        if (h.z != 0.0f) {
            atomicAdd(g + 2, h.z);
            atomicAdd(g + 3, h.w);
        }
    }

    // ---- done-counter: last block runs the tail ----
    __threadfence();
    __syncthreads();
    __shared__ int s_last;
    if (tid == 0)
        s_last = (atomicAdd(&g_done, 1) == (int)gridDim.x - 1) ? 1 : 0;
    __syncthreads();
    if (!s_last) return;

    // ---- tail: 1 bin per thread ----
    __shared__ float wtc[32], wts[32], wtp[32];
    __shared__ double wred[TPB / 32];
    __shared__ float s_npos;

    float4 h = __ldcg(&g_hist[tid]);
    g_hist[tid] = make_float4(0.f, 0.f, 0.f, 0.f);   // self-clean

    // inclusive suffix scans over 1024 threads (2 barriers)
    float ic = warp_suffix_incl(h.x, lane);
    float is = warp_suffix_incl(h.y, lane);
    float ip = warp_suffix_incl(h.z, lane);
    if (lane == 0) { wtc[wid] = ic; wts[wid] = is; wtp[wid] = ip; }
    __syncthreads();

    if (wid == 0) {
        float cc = wtc[lane], ss = wts[lane], pp = wtp[lane];
        float cci = warp_suffix_incl(cc, lane);
        float ssi = warp_suffix_incl(ss, lane);
        float ppi = warp_suffix_incl(pp, lane);
        wtc[lane] = cci - cc;      // strictly-above warp suffix
        wts[lane] = ssi - ss;
        if (lane == 0) s_npos = ppi;
    }
    if (tid == 0) g_done = 0;      // self-clean counter
    __syncthreads();

    // inclusive suffix for this bin + single dot term
    float runc = ic + wtc[wid];    // ic includes own h.x
    float runs = is + wts[wid];
    float a = h.z * runs - runc * h.w;

    for (int off = 16; off > 0; off >>= 1)
        a += __shfl_down_sync(0xFFFFFFFFu, a, off);
    if (lane == 0) wred[wid] = (double)a;
    __syncthreads();
    if (tid == 0) {
        double t = 0.0;
#pragma unroll
        for (int w = 0; w < TPB / 32; w++) t += wred[w];
        double denom = (double)fmaxf(s_npos, 1.0f);
        out[0] = (float)(t / denom);
    }
}

extern "C" void kernel_launch(void* const* d_in, const int* in_sizes, int n_in,
                              void* d_out, int out_size) {
    const float2* pred = (const float2*)d_in[0];
    const int* lab = (const int*)d_in[1];
    float* out = (float*)d_out;
    int n = in_sizes[1];

    int nblk = (n + TPB * 2 - 1) / (TPB * 2);   // 8 for N=16384
    fused_kernel<<<nblk, TPB>>>(pred, lab, n, out);
}